// round 5
// baseline (speedup 1.0000x reference)
#include <cuda_runtime.h>

#define N_PIX   6912
#define WIDTH   96
#define CFEAT   16
#define TS      64                  // column tile size
#define NTILES  (N_PIX / TS)        // 108
#define RPT     2                   // rows per thread
#define BLK     64
#define GXM     54                  // 54 * 64 * 2 = 6912 rows
#define GYM     27                  // column splits: 4 tiles per block, exact
#define NBLOCKS (GXM * GYM)         // 1458
#define PRE_BLK 32
#define PRE_GRID (N_PIX / PRE_BLK)  // 216
#define LOG2E   1.4426950408889634f

typedef unsigned long long u64;

__device__ __forceinline__ u64 pk2(float lo, float hi) {
    u64 r; asm("mov.b64 %0, {%1, %2};" : "=l"(r) : "f"(lo), "f"(hi)); return r;
}
__device__ __forceinline__ void unpk2(float& lo, float& hi, u64 v) {
    asm("mov.b64 {%0, %1}, %2;" : "=f"(lo), "=f"(hi) : "l"(v));
}
__device__ __forceinline__ u64 fma2(u64 a, u64 b, u64 c) {
    u64 r; asm("fma.rn.f32x2 %0, %1, %2, %3;" : "=l"(r) : "l"(a), "l"(b), "l"(c)); return r;
}
__device__ __forceinline__ u64 mul2(u64 a, u64 b) {
    u64 r; asm("mul.rn.f32x2 %0, %1, %2;" : "=l"(r) : "l"(a), "l"(b)); return r;
}
__device__ __forceinline__ float ex2f(float a) {
    float r; asm("ex2.approx.ftz.f32 %0, %1;" : "=f"(r) : "f"(a)); return r;
}

// colrec per pixel (24 floats = 6 float4):
// [Px, Pnx, Py, Pny | Pz, Pnz, -h2*L2E, -h2n*L2E | f2n/N x16]
__device__ float g_colrec[N_PIX * 24];
__device__ float g_part[NBLOCKS];
__device__ float g_fea1[GXM];
__device__ float g_fea2[PRE_GRID];
__device__ int   g_done = 0;

__global__ __launch_bounds__(PRE_BLK) void precompute_kernel(
    const float* __restrict__ f2, const float* __restrict__ dp2,
    const float* __restrict__ pose, const float* __restrict__ noise)
{
    int i = blockIdx.x * PRE_BLK + threadIdx.x;

    // pose_noisy = pose1_2 @ pose_noise (rows 0..2 only)
    float PN[12];
#pragma unroll
    for (int r = 0; r < 3; r++)
#pragma unroll
        for (int c = 0; c < 4; c++) {
            float s = 0.0f;
#pragma unroll
            for (int k = 0; k < 4; k++) s = fmaf(pose[r * 4 + k], noise[k * 4 + c], s);
            PN[r * 4 + c] = s;
        }

    int u = i % WIDTH, v = i / WIDTH;
    float y1 = ((float)u - 48.0f) * (1.0f / 48.0f);
    float y2 = ((float)v - 36.0f) * (1.0f / 48.0f);

    float d2 = dp2[i];
    float q0 = d2, q1 = y1 * d2, q2 = y2 * d2;
    float P[3], Pn[3];
#pragma unroll
    for (int r = 0; r < 3; r++) {
        P[r]  = fmaf(pose[r * 4 + 0], q0, fmaf(pose[r * 4 + 1], q1,
                fmaf(pose[r * 4 + 2], q2, pose[r * 4 + 3])));
        Pn[r] = fmaf(PN[r * 4 + 0], q0, fmaf(PN[r * 4 + 1], q1,
                fmaf(PN[r * 4 + 2], q2, PN[r * 4 + 3])));
    }
    float mh2  = -0.5f * LOG2E * (P[0] * P[0] + P[1] * P[1] + P[2] * P[2]);
    float mh2n = -0.5f * LOG2E * (Pn[0] * Pn[0] + Pn[1] * Pn[1] + Pn[2] * Pn[2]);

    float b[CFEAT], s2 = 0.0f;
#pragma unroll
    for (int c = 0; c < CFEAT; c++) { b[c] = f2[c * N_PIX + i]; s2 = fmaf(b[c], b[c], s2); }
    float n2 = sqrtf(s2);
    float sc = (1.0f / (n2 + 1e-8f)) * (1.0f / (float)N_PIX);

    float* cc = g_colrec + (size_t)i * 24;
    cc[0] = P[0]; cc[1] = Pn[0]; cc[2] = P[1]; cc[3] = Pn[1];
    cc[4] = P[2]; cc[5] = Pn[2]; cc[6] = mh2;  cc[7] = mh2n;
#pragma unroll
    for (int c = 0; c < CFEAT; c++) cc[8 + c] = b[c] * sc;

    // warp-shuffle reduction of f2 norms (block == 1 warp)
    float r = n2;
#pragma unroll
    for (int s = 16; s > 0; s >>= 1) r += __shfl_down_sync(0xFFFFFFFF, r, s);
    if (threadIdx.x == 0) g_fea2[blockIdx.x] = r;
}

__global__ __launch_bounds__(BLK, 8) void main_kernel(
    const float* __restrict__ f1, const float* __restrict__ dp1,
    float* __restrict__ out, int out_size)
{
    __shared__ ulonglong2 sc[TS * 6];   // 6 KB tile
    __shared__ float sred[2];
    __shared__ int s_last;

    int tid = threadIdx.x;
    int lane = tid & 31;
    int wid = tid >> 5;
    int base = blockIdx.x * (BLK * RPT);

    // Row records in registers (exp2-domain). h1 factored out:
    // e^{min(b-h1,0)} = e^{-h1} * e^{min(b,h1)}.
    u64 X[RPT], Y[RPT], Z[RPT], F[RPT][8];
    float H1L[RPT], EH1[RPT];
    float fea1 = 0.0f;
#pragma unroll
    for (int k = 0; k < RPT; k++) {
        int m = base + k * BLK + tid;
        int u = m % WIDTH, v = m / WIDTH;
        float y1 = ((float)u - 48.0f) * (1.0f / 48.0f);
        float y2 = ((float)v - 36.0f) * (1.0f / 48.0f);
        float d = dp1[m];
        float xx = d, xy = y1 * d, xz = y2 * d;
        float h1L = 0.5f * LOG2E * (xx * xx + xy * xy + xz * xz);
        float xs = xx * LOG2E, ys = xy * LOG2E, zs = xz * LOG2E;
        X[k] = pk2(xs, xs); Y[k] = pk2(ys, ys); Z[k] = pk2(zs, zs);
        H1L[k] = h1L;
        EH1[k] = ex2f(-h1L);

        float a[CFEAT], s1 = 0.0f;
#pragma unroll
        for (int c = 0; c < CFEAT; c++) { a[c] = f1[c * N_PIX + m]; s1 = fmaf(a[c], a[c], s1); }
        float n1 = sqrtf(s1);
        fea1 += n1;
        float inv = 1.0f / (n1 + 1e-8f);
#pragma unroll
        for (int c = 0; c < 8; c++) F[k][c] = pk2(a[2 * c] * inv, a[2 * c + 1] * inv);
    }

    float acc[RPT];
#pragma unroll
    for (int k = 0; k < RPT; k++) acc[k] = 0.0f;

    for (int t = blockIdx.y; t < NTILES; t += GYM) {
        __syncthreads();
        const float4* src = (const float4*)g_colrec + (size_t)t * TS * 6;
        float4* dst = (float4*)sc;
#pragma unroll
        for (int i = tid; i < TS * 6; i += BLK) dst[i] = src[i];
        __syncthreads();

#pragma unroll 2
        for (int j = 0; j < TS; j++) {
            const ulonglong2* cp = sc + j * 6;
            ulonglong2 c0 = cp[0], c1 = cp[1];
            ulonglong2 c2 = cp[2], c3 = cp[3], c4 = cp[4], c5 = cp[5];
            u64 v0 = c0.x, v1 = c0.y, v2 = c1.x, hh = c1.y;   // hh = {-h2L, -h2nL}

#pragma unroll
            for (int k = 0; k < RPT; k++) {
                u64 aa = fma2(X[k], v0, hh);
                aa = fma2(Y[k], v1, aa);
                aa = fma2(Z[k], v2, aa);
                float b1, b2; unpk2(b1, b2, aa);
                b1 = fminf(b1, H1L[k]);
                b2 = fminf(b2, H1L[k]);
                float e1 = ex2f(b1);
                float e2 = ex2f(b2);

                // gram dot: two independent 4-deep chains
                u64 dd0 = mul2(F[k][0], c2.x);
                u64 dd1 = mul2(F[k][1], c2.y);
                dd0 = fma2(F[k][2], c3.x, dd0);
                dd1 = fma2(F[k][3], c3.y, dd1);
                dd0 = fma2(F[k][4], c4.x, dd0);
                dd1 = fma2(F[k][5], c4.y, dd1);
                dd0 = fma2(F[k][6], c5.x, dd0);
                dd1 = fma2(F[k][7], c5.y, dd1);
                float g0, g1, g2, g3;
                unpk2(g0, g1, dd0);
                unpk2(g2, g3, dd1);
                acc[k] = fmaf(e1 - e2, (g0 + g1) + (g2 + g3), acc[k]);
            }
        }
    }

    // Block reduction (2 warps) of weighted accumulators.
    float a = fmaf(EH1[0], acc[0], EH1[1] * acc[1]);
#pragma unroll
    for (int s = 16; s > 0; s >>= 1) a += __shfl_down_sync(0xFFFFFFFF, a, s);
    if (lane == 0) sred[wid] = a;
    __syncthreads();
    if (tid == 0) g_part[blockIdx.x * GYM + blockIdx.y] = sred[0] + sred[1];

    if (blockIdx.y == 0) {
        float r = fea1;
#pragma unroll
        for (int s = 16; s > 0; s >>= 1) r += __shfl_down_sync(0xFFFFFFFF, r, s);
        __syncthreads();
        if (lane == 0) sred[wid] = r;
        __syncthreads();
        if (tid == 0) g_fea1[blockIdx.x] = sred[0] + sred[1];
    }

    // Last-block finalize (deterministic: fixed-order strided sums by one warp).
    if (tid == 0) {
        __threadfence();
        int prev = atomicAdd(&g_done, 1);
        s_last = (prev == NBLOCKS - 1) ? 1 : 0;
    }
    __syncthreads();
    if (s_last && wid == 0) {
        float S = 0.0f;
        for (int i = lane; i < NBLOCKS; i += 32) S += g_part[i];
        float Ff = 0.0f;
        for (int i = lane; i < GXM; i += 32) Ff += g_fea1[i];
        for (int i = lane; i < PRE_GRID; i += 32) Ff += g_fea2[i];
#pragma unroll
        for (int s = 16; s > 0; s >>= 1) {
            S  += __shfl_down_sync(0xFFFFFFFF, S, s);
            Ff += __shfl_down_sync(0xFFFFFFFF, Ff, s);
        }
        if (lane == 0) {
            float inner = -S;                        // 1/N folded into colrec features
            if (out_size > 0) out[0] = inner;        // final_loss
            if (out_size > 1) out[1] = inner;        // inner_neg
            if (out_size > 2) out[2] = Ff * 100.0f;  // fea_norm_sum
            g_done = 0;                              // reset for next replay
        }
        for (int i = 3 + lane; i < out_size; i += 32) out[i] = 0.0f;
    }
}

extern "C" void kernel_launch(void* const* d_in, const int* in_sizes, int n_in,
                              void* d_out, int out_size)
{
    const float* f1    = (const float*)d_in[0];
    const float* f2    = (const float*)d_in[1];
    const float* dp1   = (const float*)d_in[2];
    const float* dp2   = (const float*)d_in[3];
    const float* pose  = (const float*)d_in[4];
    const float* noise = (const float*)d_in[5];

    precompute_kernel<<<PRE_GRID, PRE_BLK>>>(f2, dp2, pose, noise);
    dim3 grid(GXM, GYM);
    main_kernel<<<grid, BLK>>>(f1, dp1, (float*)d_out, out_size);
}

// round 8
// speedup vs baseline: 1.0611x; 1.0611x over previous
#include <cuda_runtime.h>

#define N_PIX   6912
#define WIDTH   96
#define CFEAT   16
#define TS      64                  // column tile size
#define NTILES  (N_PIX / TS)        // 108
#define RPT     2                   // rows per thread
#define BLK     64
#define GXM     54                  // 54 * 64 * 2 = 6912 rows
#define GYM     36                  // column splits: 3 tiles per block, exact
#define NBLOCKS (GXM * GYM)         // 1944
#define PRE_BLK 32
#define PRE_GRID (N_PIX / PRE_BLK)  // 216
#define LOG2E   1.4426950408889634f

typedef unsigned long long u64;

__device__ __forceinline__ u64 pk2(float lo, float hi) {
    u64 r; asm("mov.b64 %0, {%1, %2};" : "=l"(r) : "f"(lo), "f"(hi)); return r;
}
__device__ __forceinline__ void unpk2(float& lo, float& hi, u64 v) {
    asm("mov.b64 {%0, %1}, %2;" : "=f"(lo), "=f"(hi) : "l"(v));
}
__device__ __forceinline__ u64 fma2(u64 a, u64 b, u64 c) {
    u64 r; asm("fma.rn.f32x2 %0, %1, %2, %3;" : "=l"(r) : "l"(a), "l"(b), "l"(c)); return r;
}
__device__ __forceinline__ u64 mul2(u64 a, u64 b) {
    u64 r; asm("mul.rn.f32x2 %0, %1, %2;" : "=l"(r) : "l"(a), "l"(b)); return r;
}
__device__ __forceinline__ float ex2f(float a) {
    float r; asm("ex2.approx.ftz.f32 %0, %1;" : "=f"(r) : "f"(a)); return r;
}

// colrec per pixel (24 floats = 6 float4):
// [Px, Pnx, Py, Pny | Pz, Pnz, -h2*L2E, -h2n*L2E | f2n/N x16]
__device__ float g_colrec[N_PIX * 24];
__device__ float g_part[NBLOCKS];
__device__ float g_fea1[GXM];
__device__ float g_fea2[PRE_GRID];
__device__ int   g_done = 0;

__global__ __launch_bounds__(PRE_BLK) void precompute_kernel(
    const float* __restrict__ f2, const float* __restrict__ dp2,
    const float* __restrict__ pose, const float* __restrict__ noise)
{
    int i = blockIdx.x * PRE_BLK + threadIdx.x;

    // pose_noisy = pose1_2 @ pose_noise (rows 0..2 only)
    float PN[12];
#pragma unroll
    for (int r = 0; r < 3; r++)
#pragma unroll
        for (int c = 0; c < 4; c++) {
            float s = 0.0f;
#pragma unroll
            for (int k = 0; k < 4; k++) s = fmaf(pose[r * 4 + k], noise[k * 4 + c], s);
            PN[r * 4 + c] = s;
        }

    int u = i % WIDTH, v = i / WIDTH;
    float y1 = ((float)u - 48.0f) * (1.0f / 48.0f);
    float y2 = ((float)v - 36.0f) * (1.0f / 48.0f);

    float d2 = dp2[i];
    float q0 = d2, q1 = y1 * d2, q2 = y2 * d2;
    float P[3], Pn[3];
#pragma unroll
    for (int r = 0; r < 3; r++) {
        P[r]  = fmaf(pose[r * 4 + 0], q0, fmaf(pose[r * 4 + 1], q1,
                fmaf(pose[r * 4 + 2], q2, pose[r * 4 + 3])));
        Pn[r] = fmaf(PN[r * 4 + 0], q0, fmaf(PN[r * 4 + 1], q1,
                fmaf(PN[r * 4 + 2], q2, PN[r * 4 + 3])));
    }
    float mh2  = -0.5f * LOG2E * (P[0] * P[0] + P[1] * P[1] + P[2] * P[2]);
    float mh2n = -0.5f * LOG2E * (Pn[0] * Pn[0] + Pn[1] * Pn[1] + Pn[2] * Pn[2]);

    float b[CFEAT], s2 = 0.0f;
#pragma unroll
    for (int c = 0; c < CFEAT; c++) { b[c] = f2[c * N_PIX + i]; s2 = fmaf(b[c], b[c], s2); }
    float n2 = sqrtf(s2);
    float sc = (1.0f / (n2 + 1e-8f)) * (1.0f / (float)N_PIX);

    float* cc = g_colrec + (size_t)i * 24;
    cc[0] = P[0]; cc[1] = Pn[0]; cc[2] = P[1]; cc[3] = Pn[1];
    cc[4] = P[2]; cc[5] = Pn[2]; cc[6] = mh2;  cc[7] = mh2n;
#pragma unroll
    for (int c = 0; c < CFEAT; c++) cc[8 + c] = b[c] * sc;

    // warp-shuffle reduction of f2 norms (block == 1 warp)
    float r = n2;
#pragma unroll
    for (int s = 16; s > 0; s >>= 1) r += __shfl_down_sync(0xFFFFFFFF, r, s);
    if (threadIdx.x == 0) g_fea2[blockIdx.x] = r;
}

__global__ __launch_bounds__(BLK, 10) void main_kernel(
    const float* __restrict__ f1, const float* __restrict__ dp1,
    float* __restrict__ out, int out_size)
{
    __shared__ ulonglong2 sc[TS * 6];   // 6 KB tile
    __shared__ float sred[2];
    __shared__ int s_last;

    int tid = threadIdx.x;
    int lane = tid & 31;
    int wid = tid >> 5;
    int base = blockIdx.x * (BLK * RPT);

    // Row records in registers (exp2-domain). h1 factored out:
    // e^{b-h1} = e^{-h1} * e^{b}; b - h1 <= 0 analytically, so no clamp needed
    // (row-uniform scaling keeps relative precision; validated in R5).
    u64 X[RPT], Y[RPT], Z[RPT], F[RPT][8];
    float EH1[RPT];
    float fea1 = 0.0f;
#pragma unroll
    for (int k = 0; k < RPT; k++) {
        int m = base + k * BLK + tid;
        int u = m % WIDTH, v = m / WIDTH;
        float y1 = ((float)u - 48.0f) * (1.0f / 48.0f);
        float y2 = ((float)v - 36.0f) * (1.0f / 48.0f);
        float d = dp1[m];
        float xx = d, xy = y1 * d, xz = y2 * d;
        float h1L = 0.5f * LOG2E * (xx * xx + xy * xy + xz * xz);
        float xs = xx * LOG2E, ys = xy * LOG2E, zs = xz * LOG2E;
        X[k] = pk2(xs, xs); Y[k] = pk2(ys, ys); Z[k] = pk2(zs, zs);
        EH1[k] = ex2f(-h1L);

        float a[CFEAT], s1 = 0.0f;
#pragma unroll
        for (int c = 0; c < CFEAT; c++) { a[c] = f1[c * N_PIX + m]; s1 = fmaf(a[c], a[c], s1); }
        float n1 = sqrtf(s1);
        fea1 += n1;
        float inv = 1.0f / (n1 + 1e-8f);
#pragma unroll
        for (int c = 0; c < 8; c++) F[k][c] = pk2(a[2 * c] * inv, a[2 * c + 1] * inv);
    }

    float acc[RPT];
#pragma unroll
    for (int k = 0; k < RPT; k++) acc[k] = 0.0f;

    for (int t = blockIdx.y; t < NTILES; t += GYM) {
        __syncthreads();
        const float4* src = (const float4*)g_colrec + (size_t)t * TS * 6;
        float4* dst = (float4*)sc;
#pragma unroll
        for (int i = tid; i < TS * 6; i += BLK) dst[i] = src[i];
        __syncthreads();

#pragma unroll 2
        for (int j = 0; j < TS; j++) {
            const ulonglong2* cp = sc + j * 6;
            ulonglong2 c0 = cp[0], c1 = cp[1];
            ulonglong2 c2 = cp[2], c3 = cp[3], c4 = cp[4], c5 = cp[5];
            u64 v0 = c0.x, v1 = c0.y, v2 = c1.x, hh = c1.y;   // hh = {-h2L, -h2nL}

#pragma unroll
            for (int k = 0; k < RPT; k++) {
                u64 aa = fma2(X[k], v0, hh);
                aa = fma2(Y[k], v1, aa);
                aa = fma2(Z[k], v2, aa);
                float b1, b2; unpk2(b1, b2, aa);
                float e1 = ex2f(b1);
                float e2 = ex2f(b2);

                // gram dot: two independent 4-deep chains
                u64 dd0 = mul2(F[k][0], c2.x);
                u64 dd1 = mul2(F[k][1], c2.y);
                dd0 = fma2(F[k][2], c3.x, dd0);
                dd1 = fma2(F[k][3], c3.y, dd1);
                dd0 = fma2(F[k][4], c4.x, dd0);
                dd1 = fma2(F[k][5], c4.y, dd1);
                dd0 = fma2(F[k][6], c5.x, dd0);
                dd1 = fma2(F[k][7], c5.y, dd1);
                float g0, g1, g2, g3;
                unpk2(g0, g1, dd0);
                unpk2(g2, g3, dd1);
                acc[k] = fmaf(e1 - e2, (g0 + g1) + (g2 + g3), acc[k]);
            }
        }
    }

    // Block reduction (2 warps) of weighted accumulators.
    float a = fmaf(EH1[0], acc[0], EH1[1] * acc[1]);
#pragma unroll
    for (int s = 16; s > 0; s >>= 1) a += __shfl_down_sync(0xFFFFFFFF, a, s);
    if (lane == 0) sred[wid] = a;
    __syncthreads();
    if (tid == 0) g_part[blockIdx.x * GYM + blockIdx.y] = sred[0] + sred[1];

    if (blockIdx.y == 0) {
        float r = fea1;
#pragma unroll
        for (int s = 16; s > 0; s >>= 1) r += __shfl_down_sync(0xFFFFFFFF, r, s);
        __syncthreads();
        if (lane == 0) sred[wid] = r;
        __syncthreads();
        if (tid == 0) g_fea1[blockIdx.x] = sred[0] + sred[1];
    }

    // Last-block finalize (deterministic: fixed-order strided sums by one warp).
    if (tid == 0) {
        __threadfence();
        int prev = atomicAdd(&g_done, 1);
        s_last = (prev == NBLOCKS - 1) ? 1 : 0;
    }
    __syncthreads();
    if (s_last && wid == 0) {
        float S = 0.0f;
        for (int i = lane; i < NBLOCKS; i += 32) S += g_part[i];
        float Ff = 0.0f;
        for (int i = lane; i < GXM; i += 32) Ff += g_fea1[i];
        for (int i = lane; i < PRE_GRID; i += 32) Ff += g_fea2[i];
#pragma unroll
        for (int s = 16; s > 0; s >>= 1) {
            S  += __shfl_down_sync(0xFFFFFFFF, S, s);
            Ff += __shfl_down_sync(0xFFFFFFFF, Ff, s);
        }
        if (lane == 0) {
            float inner = -S;                        // 1/N folded into colrec features
            if (out_size > 0) out[0] = inner;        // final_loss
            if (out_size > 1) out[1] = inner;        // inner_neg
            if (out_size > 2) out[2] = Ff * 100.0f;  // fea_norm_sum
            g_done = 0;                              // reset for next replay
        }
        for (int i = 3 + lane; i < out_size; i += 32) out[i] = 0.0f;
    }
}

extern "C" void kernel_launch(void* const* d_in, const int* in_sizes, int n_in,
                              void* d_out, int out_size)
{
    const float* f1    = (const float*)d_in[0];
    const float* f2    = (const float*)d_in[1];
    const float* dp1   = (const float*)d_in[2];
    const float* dp2   = (const float*)d_in[3];
    const float* pose  = (const float*)d_in[4];
    const float* noise = (const float*)d_in[5];

    precompute_kernel<<<PRE_GRID, PRE_BLK>>>(f2, dp2, pose, noise);
    dim3 grid(GXM, GYM);
    main_kernel<<<grid, BLK>>>(f1, dp1, (float*)d_out, out_size);
}

// round 9
// speedup vs baseline: 1.0637x; 1.0025x over previous
#include <cuda_runtime.h>

#define N_PIX   6912
#define WIDTH   96
#define CFEAT   16
#define TS      64                  // column tile size
#define NTILES  (N_PIX / TS)        // 108
#define RPT     2                   // rows per thread
#define BLK     64
#define GXM     54                  // 54 * 64 * 2 = 6912 rows
#define GYM     27                  // column splits: 4 contiguous tiles per block
#define TPB     (NTILES / GYM)      // 4 tiles per block
#define NBLOCKS (GXM * GYM)         // 1458  (~one wave at 10 blocks/SM)
#define PRE_BLK 32
#define PRE_GRID (N_PIX / PRE_BLK)  // 216
#define LOG2E   1.4426950408889634f

typedef unsigned long long u64;

__device__ __forceinline__ u64 pk2(float lo, float hi) {
    u64 r; asm("mov.b64 %0, {%1, %2};" : "=l"(r) : "f"(lo), "f"(hi)); return r;
}
__device__ __forceinline__ void unpk2(float& lo, float& hi, u64 v) {
    asm("mov.b64 {%0, %1}, %2;" : "=f"(lo), "=f"(hi) : "l"(v));
}
__device__ __forceinline__ u64 fma2(u64 a, u64 b, u64 c) {
    u64 r; asm("fma.rn.f32x2 %0, %1, %2, %3;" : "=l"(r) : "l"(a), "l"(b), "l"(c)); return r;
}
__device__ __forceinline__ u64 mul2(u64 a, u64 b) {
    u64 r; asm("mul.rn.f32x2 %0, %1, %2;" : "=l"(r) : "l"(a), "l"(b)); return r;
}
__device__ __forceinline__ u64 add2(u64 a, u64 b) {
    u64 r; asm("add.rn.f32x2 %0, %1, %2;" : "=l"(r) : "l"(a), "l"(b)); return r;
}
__device__ __forceinline__ float ex2f(float a) {
    float r; asm("ex2.approx.ftz.f32 %0, %1;" : "=f"(r) : "f"(a)); return r;
}

// colrec per pixel (24 floats = 6 float4):
// [Px, Pnx, Py, Pny | Pz, Pnz, -h2*L2E, -h2n*L2E | f2n/N x16]
__device__ float g_colrec[N_PIX * 24];
__device__ float g_part[NBLOCKS];
__device__ float g_fea1[GXM];
__device__ float g_fea2[PRE_GRID];
__device__ int   g_done = 0;

__global__ __launch_bounds__(PRE_BLK) void precompute_kernel(
    const float* __restrict__ f2, const float* __restrict__ dp2,
    const float* __restrict__ pose, const float* __restrict__ noise)
{
    int i = blockIdx.x * PRE_BLK + threadIdx.x;

    // pose_noisy = pose1_2 @ pose_noise (rows 0..2 only)
    float PN[12];
#pragma unroll
    for (int r = 0; r < 3; r++)
#pragma unroll
        for (int c = 0; c < 4; c++) {
            float s = 0.0f;
#pragma unroll
            for (int k = 0; k < 4; k++) s = fmaf(pose[r * 4 + k], noise[k * 4 + c], s);
            PN[r * 4 + c] = s;
        }

    int u = i % WIDTH, v = i / WIDTH;
    float y1 = ((float)u - 48.0f) * (1.0f / 48.0f);
    float y2 = ((float)v - 36.0f) * (1.0f / 48.0f);

    float d2 = dp2[i];
    float q0 = d2, q1 = y1 * d2, q2 = y2 * d2;
    float P[3], Pn[3];
#pragma unroll
    for (int r = 0; r < 3; r++) {
        P[r]  = fmaf(pose[r * 4 + 0], q0, fmaf(pose[r * 4 + 1], q1,
                fmaf(pose[r * 4 + 2], q2, pose[r * 4 + 3])));
        Pn[r] = fmaf(PN[r * 4 + 0], q0, fmaf(PN[r * 4 + 1], q1,
                fmaf(PN[r * 4 + 2], q2, PN[r * 4 + 3])));
    }
    float mh2  = -0.5f * LOG2E * (P[0] * P[0] + P[1] * P[1] + P[2] * P[2]);
    float mh2n = -0.5f * LOG2E * (Pn[0] * Pn[0] + Pn[1] * Pn[1] + Pn[2] * Pn[2]);

    float b[CFEAT], s2 = 0.0f;
#pragma unroll
    for (int c = 0; c < CFEAT; c++) { b[c] = f2[c * N_PIX + i]; s2 = fmaf(b[c], b[c], s2); }
    float n2 = sqrtf(s2);
    float sc = (1.0f / (n2 + 1e-8f)) * (1.0f / (float)N_PIX);

    float* cc = g_colrec + (size_t)i * 24;
    cc[0] = P[0]; cc[1] = Pn[0]; cc[2] = P[1]; cc[3] = Pn[1];
    cc[4] = P[2]; cc[5] = Pn[2]; cc[6] = mh2;  cc[7] = mh2n;
#pragma unroll
    for (int c = 0; c < CFEAT; c++) cc[8 + c] = b[c] * sc;

    // warp-shuffle reduction of f2 norms (block == 1 warp)
    float r = n2;
#pragma unroll
    for (int s = 16; s > 0; s >>= 1) r += __shfl_down_sync(0xFFFFFFFF, r, s);
    if (threadIdx.x == 0) g_fea2[blockIdx.x] = r;
}

__global__ __launch_bounds__(BLK, 10) void main_kernel(
    const float* __restrict__ f1, const float* __restrict__ dp1,
    float* __restrict__ out, int out_size)
{
    __shared__ ulonglong2 sc[TS * 6];   // 6 KB tile
    __shared__ float sred[2];
    __shared__ int s_last;

    int tid = threadIdx.x;
    int lane = tid & 31;
    int wid = tid >> 5;
    int base = blockIdx.x * (BLK * RPT);

    // Row records in registers (exp2-domain). h1 factored out:
    // e^{b-h1} = e^{-h1} * e^{b}; b - h1 <= 0 analytically, so no clamp needed.
    u64 X[RPT], Y[RPT], Z[RPT], F[RPT][8];
    float EH1[RPT];
    float fea1 = 0.0f;
#pragma unroll
    for (int k = 0; k < RPT; k++) {
        int m = base + k * BLK + tid;
        int u = m % WIDTH, v = m / WIDTH;
        float y1 = ((float)u - 48.0f) * (1.0f / 48.0f);
        float y2 = ((float)v - 36.0f) * (1.0f / 48.0f);
        float d = dp1[m];
        float xx = d, xy = y1 * d, xz = y2 * d;
        float h1L = 0.5f * LOG2E * (xx * xx + xy * xy + xz * xz);
        float xs = xx * LOG2E, ys = xy * LOG2E, zs = xz * LOG2E;
        X[k] = pk2(xs, xs); Y[k] = pk2(ys, ys); Z[k] = pk2(zs, zs);
        EH1[k] = ex2f(-h1L);

        float a[CFEAT], s1 = 0.0f;
#pragma unroll
        for (int c = 0; c < CFEAT; c++) { a[c] = f1[c * N_PIX + m]; s1 = fmaf(a[c], a[c], s1); }
        float n1 = sqrtf(s1);
        fea1 += n1;
        float inv = 1.0f / (n1 + 1e-8f);
#pragma unroll
        for (int c = 0; c < 8; c++) F[k][c] = pk2(a[2 * c] * inv, a[2 * c + 1] * inv);
    }

    // Packed accumulators: (sum e1*g, sum e2*g)
    u64 acc12[RPT];
#pragma unroll
    for (int k = 0; k < RPT; k++) acc12[k] = 0ULL;

    int t0 = blockIdx.y * TPB;
    for (int t = t0; t < t0 + TPB; t++) {
        __syncthreads();
        const float4* src = (const float4*)g_colrec + (size_t)t * TS * 6;
        float4* dst = (float4*)sc;
#pragma unroll
        for (int i = tid; i < TS * 6; i += BLK) dst[i] = src[i];
        __syncthreads();

#pragma unroll 2
        for (int j = 0; j < TS; j++) {
            const ulonglong2* cp = sc + j * 6;
            ulonglong2 c0 = cp[0], c1 = cp[1];
            ulonglong2 c2 = cp[2], c3 = cp[3], c4 = cp[4], c5 = cp[5];
            u64 v0 = c0.x, v1 = c0.y, v2 = c1.x, hh = c1.y;   // hh = {-h2L, -h2nL}

#pragma unroll
            for (int k = 0; k < RPT; k++) {
                u64 aa = fma2(X[k], v0, hh);
                aa = fma2(Y[k], v1, aa);
                aa = fma2(Z[k], v2, aa);
                float b1, b2; unpk2(b1, b2, aa);
                float e1 = ex2f(b1);
                float e2 = ex2f(b2);

                // gram dot: two independent 4-deep chains
                u64 dd0 = mul2(F[k][0], c2.x);
                u64 dd1 = mul2(F[k][1], c2.y);
                dd0 = fma2(F[k][2], c3.x, dd0);
                dd1 = fma2(F[k][3], c3.y, dd1);
                dd0 = fma2(F[k][4], c4.x, dd0);
                dd1 = fma2(F[k][5], c4.y, dd1);
                dd0 = fma2(F[k][6], c5.x, dd0);
                dd1 = fma2(F[k][7], c5.y, dd1);
                u64 ss = add2(dd0, dd1);
                float s0, s1; unpk2(s0, s1, ss);
                float g = s0 + s1;

                // packed accumulate: acc12 += (e1,e2) * (g,g)  (packs on alu pipe)
                acc12[k] = fma2(pk2(e1, e2), pk2(g, g), acc12[k]);
            }
        }
    }

    // Unpack: contribution = EH1 * (Σe1g − Σe2g).
    float A1, A2, B1, B2;
    unpk2(A1, A2, acc12[0]);
    unpk2(B1, B2, acc12[1]);
    float a = fmaf(EH1[0], A1 - A2, EH1[1] * (B1 - B2));
#pragma unroll
    for (int s = 16; s > 0; s >>= 1) a += __shfl_down_sync(0xFFFFFFFF, a, s);
    if (lane == 0) sred[wid] = a;
    __syncthreads();
    if (tid == 0) g_part[blockIdx.x * GYM + blockIdx.y] = sred[0] + sred[1];

    if (blockIdx.y == 0) {
        float r = fea1;
#pragma unroll
        for (int s = 16; s > 0; s >>= 1) r += __shfl_down_sync(0xFFFFFFFF, r, s);
        __syncthreads();
        if (lane == 0) sred[wid] = r;
        __syncthreads();
        if (tid == 0) g_fea1[blockIdx.x] = sred[0] + sred[1];
    }

    // Last-block finalize (deterministic: fixed-order strided sums by one warp).
    if (tid == 0) {
        __threadfence();
        int prev = atomicAdd(&g_done, 1);
        s_last = (prev == NBLOCKS - 1) ? 1 : 0;
    }
    __syncthreads();
    if (s_last && wid == 0) {
        float S = 0.0f;
        for (int i = lane; i < NBLOCKS; i += 32) S += g_part[i];
        float Ff = 0.0f;
        for (int i = lane; i < GXM; i += 32) Ff += g_fea1[i];
        for (int i = lane; i < PRE_GRID; i += 32) Ff += g_fea2[i];
#pragma unroll
        for (int s = 16; s > 0; s >>= 1) {
            S  += __shfl_down_sync(0xFFFFFFFF, S, s);
            Ff += __shfl_down_sync(0xFFFFFFFF, Ff, s);
        }
        if (lane == 0) {
            float inner = -S;                        // 1/N folded into colrec features
            if (out_size > 0) out[0] = inner;        // final_loss
            if (out_size > 1) out[1] = inner;        // inner_neg
            if (out_size > 2) out[2] = Ff * 100.0f;  // fea_norm_sum
            g_done = 0;                              // reset for next replay
        }
        for (int i = 3 + lane; i < out_size; i += 32) out[i] = 0.0f;
    }
}

extern "C" void kernel_launch(void* const* d_in, const int* in_sizes, int n_in,
                              void* d_out, int out_size)
{
    const float* f1    = (const float*)d_in[0];
    const float* f2    = (const float*)d_in[1];
    const float* dp1   = (const float*)d_in[2];
    const float* dp2   = (const float*)d_in[3];
    const float* pose  = (const float*)d_in[4];
    const float* noise = (const float*)d_in[5];

    precompute_kernel<<<PRE_GRID, PRE_BLK>>>(f2, dp2, pose, noise);
    dim3 grid(GXM, GYM);
    main_kernel<<<grid, BLK>>>(f1, dp1, (float*)d_out, out_size);
}

// round 10
// speedup vs baseline: 1.0643x; 1.0005x over previous
#include <cuda_runtime.h>

#define N_PIX   6912
#define WIDTH   96
#define CFEAT   16
#define TS      64                  // column tile size
#define NTILES  (N_PIX / TS)        // 108
#define RPT     2                   // rows per thread
#define BLK     64
#define GXM     54                  // 54 * 64 * 2 = 6912 rows
#define GYM     27                  // column splits: 4 contiguous tiles per block
#define TPB     (NTILES / GYM)      // 4 tiles per block
#define NBLOCKS (GXM * GYM)         // 1458  (~one wave)
#define PRE_BLK 32
#define PRE_GRID (N_PIX / PRE_BLK)  // 216
#define LOG2E   1.4426950408889634f
#define CPT     6                   // ulonglong2 per column

typedef unsigned long long u64;

__device__ __forceinline__ u64 pk2(float lo, float hi) {
    u64 r; asm("mov.b64 %0, {%1, %2};" : "=l"(r) : "f"(lo), "f"(hi)); return r;
}
__device__ __forceinline__ void unpk2(float& lo, float& hi, u64 v) {
    asm("mov.b64 {%0, %1}, %2;" : "=f"(lo), "=f"(hi) : "l"(v));
}
__device__ __forceinline__ u64 fma2(u64 a, u64 b, u64 c) {
    u64 r; asm("fma.rn.f32x2 %0, %1, %2, %3;" : "=l"(r) : "l"(a), "l"(b), "l"(c)); return r;
}
__device__ __forceinline__ u64 mul2(u64 a, u64 b) {
    u64 r; asm("mul.rn.f32x2 %0, %1, %2;" : "=l"(r) : "l"(a), "l"(b)); return r;
}
__device__ __forceinline__ u64 add2(u64 a, u64 b) {
    u64 r; asm("add.rn.f32x2 %0, %1, %2;" : "=l"(r) : "l"(a), "l"(b)); return r;
}
__device__ __forceinline__ float ex2f(float a) {
    float r; asm("ex2.approx.ftz.f32 %0, %1;" : "=f"(r) : "f"(a)); return r;
}

// colrec per pixel (24 floats = 6 float4):
// [Px, Pnx, Py, Pny | Pz, Pnz, -h2*L2E, -h2n*L2E | f2n/N x16]
__device__ float g_colrec[N_PIX * 24];
__device__ float g_part[NBLOCKS];
__device__ float g_fea1[GXM];
__device__ float g_fea2[PRE_GRID];
__device__ int   g_done = 0;

__global__ __launch_bounds__(PRE_BLK) void precompute_kernel(
    const float* __restrict__ f2, const float* __restrict__ dp2,
    const float* __restrict__ pose, const float* __restrict__ noise)
{
    int i = blockIdx.x * PRE_BLK + threadIdx.x;

    float PN[12];
#pragma unroll
    for (int r = 0; r < 3; r++)
#pragma unroll
        for (int c = 0; c < 4; c++) {
            float s = 0.0f;
#pragma unroll
            for (int k = 0; k < 4; k++) s = fmaf(pose[r * 4 + k], noise[k * 4 + c], s);
            PN[r * 4 + c] = s;
        }

    int u = i % WIDTH, v = i / WIDTH;
    float y1 = ((float)u - 48.0f) * (1.0f / 48.0f);
    float y2 = ((float)v - 36.0f) * (1.0f / 48.0f);

    float d2 = dp2[i];
    float q0 = d2, q1 = y1 * d2, q2 = y2 * d2;
    float P[3], Pn[3];
#pragma unroll
    for (int r = 0; r < 3; r++) {
        P[r]  = fmaf(pose[r * 4 + 0], q0, fmaf(pose[r * 4 + 1], q1,
                fmaf(pose[r * 4 + 2], q2, pose[r * 4 + 3])));
        Pn[r] = fmaf(PN[r * 4 + 0], q0, fmaf(PN[r * 4 + 1], q1,
                fmaf(PN[r * 4 + 2], q2, PN[r * 4 + 3])));
    }
    float mh2  = -0.5f * LOG2E * (P[0] * P[0] + P[1] * P[1] + P[2] * P[2]);
    float mh2n = -0.5f * LOG2E * (Pn[0] * Pn[0] + Pn[1] * Pn[1] + Pn[2] * Pn[2]);

    float b[CFEAT], s2 = 0.0f;
#pragma unroll
    for (int c = 0; c < CFEAT; c++) { b[c] = f2[c * N_PIX + i]; s2 = fmaf(b[c], b[c], s2); }
    float n2 = sqrtf(s2);
    float sc = (1.0f / (n2 + 1e-8f)) * (1.0f / (float)N_PIX);

    float* cc = g_colrec + (size_t)i * 24;
    cc[0] = P[0]; cc[1] = Pn[0]; cc[2] = P[1]; cc[3] = Pn[1];
    cc[4] = P[2]; cc[5] = Pn[2]; cc[6] = mh2;  cc[7] = mh2n;
#pragma unroll
    for (int c = 0; c < CFEAT; c++) cc[8 + c] = b[c] * sc;

    float r = n2;
#pragma unroll
    for (int s = 16; s > 0; s >>= 1) r += __shfl_down_sync(0xFFFFFFFF, r, s);
    if (threadIdx.x == 0) g_fea2[blockIdx.x] = r;
}

__global__ __launch_bounds__(BLK, 9) void main_kernel(
    const float* __restrict__ f1, const float* __restrict__ dp1,
    float* __restrict__ out, int out_size)
{
    // two tile buffers + 2-entry pad for the j=63 geometry prefetch
    __shared__ ulonglong2 sc[2 * TS * CPT + 2];
    __shared__ float sred[2];
    __shared__ int s_last;

    int tid = threadIdx.x;
    int lane = tid & 31;
    int wid = tid >> 5;
    int base = blockIdx.x * (BLK * RPT);

    u64 X[RPT], Y[RPT], Z[RPT], F[RPT][8];
    float EH1[RPT];
    float fea1 = 0.0f;
#pragma unroll
    for (int k = 0; k < RPT; k++) {
        int m = base + k * BLK + tid;
        int u = m % WIDTH, v = m / WIDTH;
        float y1 = ((float)u - 48.0f) * (1.0f / 48.0f);
        float y2 = ((float)v - 36.0f) * (1.0f / 48.0f);
        float d = dp1[m];
        float xx = d, xy = y1 * d, xz = y2 * d;
        float h1L = 0.5f * LOG2E * (xx * xx + xy * xy + xz * xz);
        float xs = xx * LOG2E, ys = xy * LOG2E, zs = xz * LOG2E;
        X[k] = pk2(xs, xs); Y[k] = pk2(ys, ys); Z[k] = pk2(zs, zs);
        EH1[k] = ex2f(-h1L);

        float a[CFEAT], s1 = 0.0f;
#pragma unroll
        for (int c = 0; c < CFEAT; c++) { a[c] = f1[c * N_PIX + m]; s1 = fmaf(a[c], a[c], s1); }
        float n1 = sqrtf(s1);
        fea1 += n1;
        float inv = 1.0f / (n1 + 1e-8f);
#pragma unroll
        for (int c = 0; c < 8; c++) F[k][c] = pk2(a[2 * c] * inv, a[2 * c + 1] * inv);
    }

    u64 acc12[RPT];
#pragma unroll
    for (int k = 0; k < RPT; k++) acc12[k] = 0ULL;

    int t0 = blockIdx.y * TPB;

    // async prologue: load first tile into buffer 0
    {
        const float4* src = (const float4*)g_colrec + (size_t)t0 * TS * CPT;
#pragma unroll
        for (int i = 0; i < CPT; i++) {
            int idx = tid + i * BLK;
            unsigned sa = (unsigned)__cvta_generic_to_shared(sc + idx);
            asm volatile("cp.async.ca.shared.global [%0], [%1], 16;"
                         :: "r"(sa), "l"(src + idx) : "memory");
        }
        asm volatile("cp.async.commit_group;" ::: "memory");
    }

    for (int ti = 0; ti < TPB; ti++) {
        // issue next tile load into the other buffer (overlaps this tile's compute)
        if (ti + 1 < TPB) {
            const float4* src = (const float4*)g_colrec + (size_t)(t0 + ti + 1) * TS * CPT;
            ulonglong2* dstb = sc + ((ti + 1) & 1) * (TS * CPT);
#pragma unroll
            for (int i = 0; i < CPT; i++) {
                int idx = tid + i * BLK;
                unsigned sa = (unsigned)__cvta_generic_to_shared(dstb + idx);
                asm volatile("cp.async.ca.shared.global [%0], [%1], 16;"
                             :: "r"(sa), "l"(src + idx) : "memory");
            }
            asm volatile("cp.async.commit_group;" ::: "memory");
            asm volatile("cp.async.wait_group 1;" ::: "memory");
        } else {
            asm volatile("cp.async.wait_group 0;" ::: "memory");
        }
        __syncthreads();   // this tile's buffer visible to all warps

        const ulonglong2* cb = sc + (ti & 1) * (TS * CPT);

        // geometry register prefetch of column 0
        u64 nv0, nv1, nv2, nhh;
        { ulonglong2 a0 = cb[0], a1 = cb[1]; nv0 = a0.x; nv1 = a0.y; nv2 = a1.x; nhh = a1.y; }

#pragma unroll 2
        for (int j = 0; j < TS; j++) {
            u64 v0 = nv0, v1 = nv1, v2 = nv2, hh = nhh;
            // prefetch next column's geometry (pad covers j=63)
            { const ulonglong2* np = cb + (j + 1) * CPT;
              ulonglong2 a0 = np[0], a1 = np[1];
              nv0 = a0.x; nv1 = a0.y; nv2 = a1.x; nhh = a1.y; }

            const ulonglong2* cp = cb + j * CPT;
            ulonglong2 c2 = cp[2], c3 = cp[3], c4 = cp[4], c5 = cp[5];

#pragma unroll
            for (int k = 0; k < RPT; k++) {
                u64 aa = fma2(X[k], v0, hh);
                aa = fma2(Y[k], v1, aa);
                aa = fma2(Z[k], v2, aa);
                float b1, b2; unpk2(b1, b2, aa);
                float e1 = ex2f(b1);
                float e2 = ex2f(b2);

                u64 dd0 = mul2(F[k][0], c2.x);
                u64 dd1 = mul2(F[k][1], c2.y);
                dd0 = fma2(F[k][2], c3.x, dd0);
                dd1 = fma2(F[k][3], c3.y, dd1);
                dd0 = fma2(F[k][4], c4.x, dd0);
                dd1 = fma2(F[k][5], c4.y, dd1);
                dd0 = fma2(F[k][6], c5.x, dd0);
                dd1 = fma2(F[k][7], c5.y, dd1);
                u64 ss = add2(dd0, dd1);
                float s0, s1v; unpk2(s0, s1v, ss);
                float g = s0 + s1v;

                acc12[k] = fma2(pk2(e1, e2), pk2(g, g), acc12[k]);
            }
        }
        __syncthreads();   // done with this buffer before it is refilled
    }

    float A1, A2, B1, B2;
    unpk2(A1, A2, acc12[0]);
    unpk2(B1, B2, acc12[1]);
    float a = fmaf(EH1[0], A1 - A2, EH1[1] * (B1 - B2));
#pragma unroll
    for (int s = 16; s > 0; s >>= 1) a += __shfl_down_sync(0xFFFFFFFF, a, s);
    if (lane == 0) sred[wid] = a;
    __syncthreads();
    if (tid == 0) g_part[blockIdx.x * GYM + blockIdx.y] = sred[0] + sred[1];

    if (blockIdx.y == 0) {
        float r = fea1;
#pragma unroll
        for (int s = 16; s > 0; s >>= 1) r += __shfl_down_sync(0xFFFFFFFF, r, s);
        __syncthreads();
        if (lane == 0) sred[wid] = r;
        __syncthreads();
        if (tid == 0) g_fea1[blockIdx.x] = sred[0] + sred[1];
    }

    if (tid == 0) {
        __threadfence();
        int prev = atomicAdd(&g_done, 1);
        s_last = (prev == NBLOCKS - 1) ? 1 : 0;
    }
    __syncthreads();
    if (s_last && wid == 0) {
        float S = 0.0f;
        for (int i = lane; i < NBLOCKS; i += 32) S += g_part[i];
        float Ff = 0.0f;
        for (int i = lane; i < GXM; i += 32) Ff += g_fea1[i];
        for (int i = lane; i < PRE_GRID; i += 32) Ff += g_fea2[i];
#pragma unroll
        for (int s = 16; s > 0; s >>= 1) {
            S  += __shfl_down_sync(0xFFFFFFFF, S, s);
            Ff += __shfl_down_sync(0xFFFFFFFF, Ff, s);
        }
        if (lane == 0) {
            float inner = -S;
            if (out_size > 0) out[0] = inner;        // final_loss
            if (out_size > 1) out[1] = inner;        // inner_neg
            if (out_size > 2) out[2] = Ff * 100.0f;  // fea_norm_sum
            g_done = 0;
        }
        for (int i = 3 + lane; i < out_size; i += 32) out[i] = 0.0f;
    }
}

extern "C" void kernel_launch(void* const* d_in, const int* in_sizes, int n_in,
                              void* d_out, int out_size)
{
    const float* f1    = (const float*)d_in[0];
    const float* f2    = (const float*)d_in[1];
    const float* dp1   = (const float*)d_in[2];
    const float* dp2   = (const float*)d_in[3];
    const float* pose  = (const float*)d_in[4];
    const float* noise = (const float*)d_in[5];

    precompute_kernel<<<PRE_GRID, PRE_BLK>>>(f2, dp2, pose, noise);
    dim3 grid(GXM, GYM);
    main_kernel<<<grid, BLK>>>(f1, dp1, (float*)d_out, out_size);
}